// round 5
// baseline (speedup 1.0000x reference)
#include <cuda_runtime.h>

// ---------------- static problem config ----------------
// B=2, T=8, H=64, W=64, C=128; windows: T_SP=2, H_SP=64, W_SP=4
// NUM_HEADS=4, HEAD_DIM=32, N=512 tokens/window, nW=128, L=32768
#define Bc   2
#define Tc   8
#define Hc   64
#define Wc   64
#define Cc   128
#define TSP  2
#define HSP  64
#define WSP  4
#define NH   4
#define HD   32
#define NTOK 512
#define Lc   (Tc * Hc * Wc)          // 32768
#define SCALE_F 0.17677669529663687f // 32^-0.5

// smem: K(512x32) + V(512x32) + conv w (27x32, [j][d]) + bias(32)
#define SMEM_FLOATS (NTOK * HD * 2 + 27 * HD + HD)
#define SMEM_BYTES  (SMEM_FLOATS * 4)

__global__ void __launch_bounds__(512, 1)
lepe_attn_kernel(const float* __restrict__ qkv,
                 const float* __restrict__ lepe_w,
                 const float* __restrict__ lepe_b,
                 float* __restrict__ out)
{
    extern __shared__ float sm[];
    float* k_sm = sm;                   // [512][32]
    float* v_sm = sm + NTOK * HD;       // [512][32]
    float* w_sm = v_sm + NTOK * HD;     // [27][32]
    float* b_sm = w_sm + 27 * HD;       // [32]

    const int wh   = blockIdx.x;        // 0..511
    const int head = wh & 3;
    const int w    = wh >> 2;           // window id 0..127
    const int b    = w >> 6;            // batch
    const int tb   = (w >> 4) & 3;      // T-block
    const int wb   = w & 15;            // W-block
    const int cbase = head * HD;

    const float* qg = qkv + (size_t)b * Lc * Cc;
    const float* kg = qkv + (size_t)Bc * Lc * Cc + (size_t)b * Lc * Cc;
    const float* vg = qkv + 2 * (size_t)Bc * Lc * Cc + (size_t)b * Lc * Cc;

    const int tid = threadIdx.x;

    // ---- cooperative load: K, V tiles (512 tokens x 8 float4) ----
    for (int idx = tid; idx < NTOK * 8; idx += 512) {
        int tok = idx >> 3;
        int f   = idx & 7;
        int ts  = tok >> 8;             // tok / (HSP*WSP)
        int hs  = (tok >> 2) & 63;
        int ws  = tok & 3;
        int l   = ((tb * TSP + ts) * Hc + hs) * Wc + wb * WSP + ws;
        size_t off = (size_t)l * Cc + cbase + f * 4;
        *(float4*)(k_sm + tok * HD + f * 4) = *(const float4*)(kg + off);
        *(float4*)(v_sm + tok * HD + f * 4) = *(const float4*)(vg + off);
    }
    // conv weights -> [j][d] (broadcast-friendly)
    for (int idx = tid; idx < 27 * HD; idx += 512) {
        int d = idx & 31;
        int j = idx >> 5;
        w_sm[j * HD + d] = lepe_w[(size_t)(cbase + d) * 27 + j];
    }
    if (tid < HD) b_sm[tid] = lepe_b[cbase + tid];

    // ---- own query row ----
    const int n  = tid;
    const int ts = n >> 8;
    const int hs = (n >> 2) & 63;
    const int ws = n & 3;
    const int l  = ((tb * TSP + ts) * Hc + hs) * Wc + wb * WSP + ws;

    float q[HD];
    {
        const float4* qp = (const float4*)(qg + (size_t)l * Cc + cbase);
        #pragma unroll
        for (int f = 0; f < 8; f++) {
            float4 t4 = qp[f];
            q[f*4+0] = t4.x * SCALE_F; q[f*4+1] = t4.y * SCALE_F;
            q[f*4+2] = t4.z * SCALE_F; q[f*4+3] = t4.w * SCALE_F;
        }
    }
    __syncthreads();

    // ---- flash attention over 512 keys, 16-wide score tiles ----
    float acc[HD];
    #pragma unroll
    for (int d = 0; d < HD; d++) acc[d] = 0.f;
    float mx = -3.0e38f, lsum = 0.f;

    for (int m0 = 0; m0 < NTOK; m0 += 16) {
        float s[16];
        #pragma unroll
        for (int j = 0; j < 16; j++) {
            const float4* kp = (const float4*)(k_sm + (m0 + j) * HD);
            float s0 = 0.f, s1 = 0.f, s2 = 0.f, s3 = 0.f;
            #pragma unroll
            for (int d4 = 0; d4 < 8; d4++) {
                float4 kv = kp[d4];
                s0 += q[d4*4+0] * kv.x;
                s1 += q[d4*4+1] * kv.y;
                s2 += q[d4*4+2] * kv.z;
                s3 += q[d4*4+3] * kv.w;
            }
            s[j] = (s0 + s1) + (s2 + s3);
        }
        float tmax = s[0];
        #pragma unroll
        for (int j = 1; j < 16; j++) tmax = fmaxf(tmax, s[j]);
        float nmx = fmaxf(mx, tmax);
        float f = __expf(mx - nmx);     // 0 on first tile (exp(-inf))
        mx = nmx;
        lsum *= f;
        #pragma unroll
        for (int d = 0; d < HD; d++) acc[d] *= f;
        #pragma unroll
        for (int j = 0; j < 16; j++) {
            float p = __expf(s[j] - mx);
            lsum += p;
            const float4* vp = (const float4*)(v_sm + (m0 + j) * HD);
            #pragma unroll
            for (int d4 = 0; d4 < 8; d4++) {
                float4 vv = vp[d4];
                acc[d4*4+0] += p * vv.x;
                acc[d4*4+1] += p * vv.y;
                acc[d4*4+2] += p * vv.z;
                acc[d4*4+3] += p * vv.w;
            }
        }
    }

    const float inv = 1.0f / lsum;
    #pragma unroll
    for (int d = 0; d < HD; d++) acc[d] = acc[d] * inv + b_sm[d];

    // ---- fused LePE depthwise 3x3x3 conv (SAME, zero-pad inside window) ----
    #pragma unroll
    for (int kt = -1; kt <= 1; kt++) {
        int tt = ts + kt;
        if (tt < 0 || tt >= TSP) continue;
        #pragma unroll
        for (int kh = -1; kh <= 1; kh++) {
            int hh = hs + kh;
            if (hh < 0 || hh >= HSP) continue;
            #pragma unroll
            for (int kw = -1; kw <= 1; kw++) {
                int wwi = ws + kw;
                if (wwi < 0 || wwi >= WSP) continue;
                int mm = (tt * HSP + hh) * WSP + wwi;
                int j  = (kt + 1) * 9 + (kh + 1) * 3 + (kw + 1);
                const float4* vp = (const float4*)(v_sm + mm * HD);
                const float4* wp = (const float4*)(w_sm + j * HD);
                #pragma unroll
                for (int d4 = 0; d4 < 8; d4++) {
                    float4 vv = vp[d4];
                    float4 wv = wp[d4];
                    acc[d4*4+0] += wv.x * vv.x;
                    acc[d4*4+1] += wv.y * vv.y;
                    acc[d4*4+2] += wv.z * vv.z;
                    acc[d4*4+3] += wv.w * vv.w;
                }
            }
        }
    }

    // ---- write output (B, L, C) ----
    float* op = out + (size_t)b * Lc * Cc + (size_t)l * Cc + cbase;
    #pragma unroll
    for (int f = 0; f < 8; f++) {
        *(float4*)(op + f * 4) =
            make_float4(acc[f*4+0], acc[f*4+1], acc[f*4+2], acc[f*4+3]);
    }
}

extern "C" void kernel_launch(void* const* d_in, const int* in_sizes, int n_in,
                              void* d_out, int out_size)
{
    const float* qkv    = (const float*)d_in[0];
    const float* lepe_w = (const float*)d_in[1];
    const float* lepe_b = (const float*)d_in[2];
    float* out          = (float*)d_out;

    cudaFuncSetAttribute(lepe_attn_kernel,
                         cudaFuncAttributeMaxDynamicSharedMemorySize,
                         SMEM_BYTES);

    lepe_attn_kernel<<<Bc * (Tc / TSP) * (Wc / WSP) * NH, 512, SMEM_BYTES>>>(
        qkv, lepe_w, lepe_b, out);
}

// round 8
// speedup vs baseline: 5.1173x; 5.1173x over previous
#include <cuda_runtime.h>
#include <cuda_fp16.h>
#include <cstdint>

// ---------------- static problem config ----------------
#define Bc 2
#define Tc 8
#define Hc 64
#define Wc 64
#define Cc 128
#define TSP 2
#define HSP 64
#define WSP 4
#define HD 32
#define NTOK 512
#define Lc (Tc*Hc*Wc)
#define SCALE_F 0.17677669529663687f

// ---------------- smem layout (bytes) ----------------
// Qs, Ks, Vs: 512 rows x 40 halves (80B rows, conflict-free frag loads)
// Vts: 32 rows x 520 halves (1040B rows)
// Osm: 512 rows x 34 floats
#define QS_OFF   0
#define KS_OFF   40960
#define VS_OFF   81920
#define VTS_OFF  122880
#define OSM_OFF  156160
#define W_OFF    225792
#define B_OFF    229248
#define SM_TOTAL 229376

static __device__ __forceinline__ void mma_f16(float* d, const uint32_t* a, const uint32_t* b) {
    asm volatile(
        "mma.sync.aligned.m16n8k16.row.col.f32.f16.f16.f32 "
        "{%0,%1,%2,%3}, {%4,%5,%6,%7}, {%8,%9}, {%0,%1,%2,%3};"
        : "+f"(d[0]), "+f"(d[1]), "+f"(d[2]), "+f"(d[3])
        : "r"(a[0]), "r"(a[1]), "r"(a[2]), "r"(a[3]), "r"(b[0]), "r"(b[1]));
}

// exp(x) on the FMA pipe: 2^(x*log2e) via magic-round + deg-4 poly + exponent add
static __device__ __forceinline__ float fast_exp(float x) {
    float t = x * 1.4426950408889634f;
    float r = t + 12582912.0f;                 // round-to-nearest int in mantissa
    float f = t - (r - 12582912.0f);           // f in [-0.5, 0.5]
    float p = 0.00961804886f;
    p = fmaf(p, f, 0.0555036958f);
    p = fmaf(p, f, 0.240226344f);
    p = fmaf(p, f, 0.693147180f);
    p = fmaf(p, f, 1.0f);
    // bits(r)<<23 == i<<23 exactly (low 9 bits of 0x4B400000 are zero)
    return __int_as_float(__float_as_int(p) + (__float_as_int(r) << 23));
}

static __device__ __forceinline__ uint32_t pack_h2(float a, float b) {
    __half2 h = __floats2half2_rn(a, b);
    return reinterpret_cast<uint32_t&>(h);
}

__global__ void __launch_bounds__(512, 1)
lepe_attn_hmma(const float* __restrict__ qkv, const float* __restrict__ lepe_w,
               const float* __restrict__ lepe_b, float* __restrict__ out)
{
    extern __shared__ char smem[];
    __half* Qs  = (__half*)(smem + QS_OFF);    // [512][40]
    __half* Ks  = (__half*)(smem + KS_OFF);    // [512][40]
    __half* Vs  = (__half*)(smem + VS_OFF);    // [512][40]
    __half* Vts = (__half*)(smem + VTS_OFF);   // [32][520]
    float*  Osm = (float*)(smem + OSM_OFF);    // [512][34]
    float*  Wsm = (float*)(smem + W_OFF);      // [27][32]
    float*  Bsm = (float*)(smem + B_OFF);      // [32]

    const int tid  = threadIdx.x;
    const int lane = tid & 31;
    const int warp = tid >> 5;
    const int r    = lane >> 2;      // group id 0..7
    const int tg   = lane & 3;       // thread-in-group

    const int wh = blockIdx.x;
    const int head = wh & 3;
    const int w  = wh >> 2;
    const int b  = w >> 6;
    const int tb = (w >> 4) & 3;
    const int wb = w & 15;
    const int cbase = head * HD;

    const float* qg = qkv + (size_t)b * Lc * Cc;
    const float* kg = qkv + (size_t)(Bc + b) * Lc * Cc;
    const float* vg = qkv + (size_t)(2 * Bc + b) * Lc * Cc;

    // ---- cooperative load: Q,K,V -> fp16 smem (+ V transposed copy) ----
    for (int idx = tid; idx < NTOK * 8; idx += 512) {
        int tok = idx >> 3;
        int f   = idx & 7;
        int ts  = tok >> 8;
        int hs  = (tok >> 2) & 63;
        int ws  = tok & 3;
        int l   = ((tb * TSP + ts) * Hc + hs) * Wc + wb * WSP + ws;
        size_t off = (size_t)l * Cc + cbase + f * 4;
        float4 fq = *(const float4*)(qg + off);
        float4 fk = *(const float4*)(kg + off);
        float4 fv = *(const float4*)(vg + off);

        __half2* qd = (__half2*)(Qs + tok * 40 + f * 4);
        qd[0] = __floats2half2_rn(fq.x * SCALE_F, fq.y * SCALE_F);
        qd[1] = __floats2half2_rn(fq.z * SCALE_F, fq.w * SCALE_F);
        __half2* kd = (__half2*)(Ks + tok * 40 + f * 4);
        kd[0] = __floats2half2_rn(fk.x, fk.y);
        kd[1] = __floats2half2_rn(fk.z, fk.w);
        __half2* vd = (__half2*)(Vs + tok * 40 + f * 4);
        vd[0] = __floats2half2_rn(fv.x, fv.y);
        vd[1] = __floats2half2_rn(fv.z, fv.w);
        Vts[(f * 4 + 0) * 520 + tok] = __float2half_rn(fv.x);
        Vts[(f * 4 + 1) * 520 + tok] = __float2half_rn(fv.y);
        Vts[(f * 4 + 2) * 520 + tok] = __float2half_rn(fv.z);
        Vts[(f * 4 + 3) * 520 + tok] = __float2half_rn(fv.w);
    }
    for (int idx = tid; idx < 27 * HD; idx += 512) {
        int d = idx & 31, j = idx >> 5;
        Wsm[j * HD + d] = lepe_w[(size_t)(cbase + d) * 27 + j];
    }
    if (tid < HD) Bsm[tid] = lepe_b[cbase + tid];
    __syncthreads();

    // ---- per-warp: 32 query rows (2 m16 tiles), flash over 16 chunks of 32 keys ----
    const int qbase = warp * 32;

    uint32_t qa[2][2][4];                 // [m][kstep(d16)][4]
    #pragma unroll
    for (int m = 0; m < 2; m++) {
        const uint32_t* q0 = (const uint32_t*)(Qs + (qbase + 16 * m + r) * 40);
        const uint32_t* q8 = (const uint32_t*)(Qs + (qbase + 16 * m + r + 8) * 40);
        #pragma unroll
        for (int ks = 0; ks < 2; ks++) {
            qa[m][ks][0] = q0[8 * ks + tg];
            qa[m][ks][1] = q8[8 * ks + tg];
            qa[m][ks][2] = q0[8 * ks + tg + 4];
            qa[m][ks][3] = q8[8 * ks + tg + 4];
        }
    }

    float o[2][4][4];
    #pragma unroll
    for (int m = 0; m < 2; m++)
        #pragma unroll
        for (int nd = 0; nd < 4; nd++)
            #pragma unroll
            for (int k = 0; k < 4; k++) o[m][nd][k] = 0.f;
    float lsum[2][2] = {{0.f, 0.f}, {0.f, 0.f}};

    #pragma unroll 1
    for (int chunk = 0; chunk < 16; chunk++) {
        const int kb = chunk * 32;

        // S = Q * K^T  (fp32 acc)
        float s[2][4][4];
        #pragma unroll
        for (int m = 0; m < 2; m++)
            #pragma unroll
            for (int nt = 0; nt < 4; nt++)
                #pragma unroll
                for (int k = 0; k < 4; k++) s[m][nt][k] = 0.f;

        #pragma unroll
        for (int nt = 0; nt < 4; nt++) {
            const uint32_t* krow = (const uint32_t*)(Ks + (kb + nt * 8 + r) * 40);
            #pragma unroll
            for (int ks = 0; ks < 2; ks++) {
                uint32_t bb[2];
                bb[0] = krow[8 * ks + tg];
                bb[1] = krow[8 * ks + tg + 4];
                mma_f16(s[0][nt], qa[0][ks], bb);
                mma_f16(s[1][nt], qa[1][ks], bb);
            }
        }

        // exp -> lsum, pack P into A-fragment layout
        uint32_t pa[2][2][4];             // [m][kp(key16)][4]
        #pragma unroll
        for (int m = 0; m < 2; m++) {
            #pragma unroll
            for (int nt = 0; nt < 4; nt++) {
                float p0 = fast_exp(s[m][nt][0]);
                float p1 = fast_exp(s[m][nt][1]);
                float p2 = fast_exp(s[m][nt][2]);
                float p3 = fast_exp(s[m][nt][3]);
                lsum[m][0] += p0 + p1;
                lsum[m][1] += p2 + p3;
                int kp = nt >> 1;
                int hiidx = (nt & 1) * 2;  // 0 or 2
                pa[m][kp][hiidx + 0] = pack_h2(p0, p1);
                pa[m][kp][hiidx + 1] = pack_h2(p2, p3);
            }
        }
        // NOTE: pa mapping — A(m16k16) regs: {a0,a1}=cols kp*16+2tg(+1) rows r/r+8
        // come from n-tile 2kp (its c0..c3); {a2,a3} from n-tile 2kp+1. The
        // hiidx layout above stores [c0c1, c2c3] of tile 2kp at [0,1] and of
        // tile 2kp+1 at [2,3] — exactly the required order.

        // O += P * V
        #pragma unroll
        for (int nd = 0; nd < 4; nd++) {
            const uint32_t* vrow = (const uint32_t*)(Vts + (8 * nd + r) * 520);
            #pragma unroll
            for (int kp = 0; kp < 2; kp++) {
                uint32_t vb[2];
                vb[0] = vrow[kb / 2 + 8 * kp + tg];
                vb[1] = vrow[kb / 2 + 8 * kp + tg + 4];
                mma_f16(o[0][nd], pa[0][kp], vb);
                mma_f16(o[1][nd], pa[1][kp], vb);
            }
        }
    }

    // ---- row-sum reduction across the 4 lanes sharing each row ----
    #pragma unroll
    for (int m = 0; m < 2; m++)
        #pragma unroll
        for (int h = 0; h < 2; h++) {
            float v = lsum[m][h];
            v += __shfl_xor_sync(0xFFFFFFFFu, v, 1);
            v += __shfl_xor_sync(0xFFFFFFFFu, v, 2);
            lsum[m][h] = 1.0f / v;
        }

    // ---- normalized O -> smem (stride 34 floats) ----
    #pragma unroll
    for (int m = 0; m < 2; m++) {
        #pragma unroll
        for (int nd = 0; nd < 4; nd++) {
            int row0 = qbase + 16 * m + r;
            int col  = 8 * nd + 2 * tg;
            float2* p0 = (float2*)(Osm + row0 * 34 + col);
            p0[0] = make_float2(o[m][nd][0] * lsum[m][0], o[m][nd][1] * lsum[m][0]);
            float2* p1 = (float2*)(Osm + (row0 + 8) * 34 + col);
            p1[0] = make_float2(o[m][nd][2] * lsum[m][1], o[m][nd][3] * lsum[m][1]);
        }
    }
    __syncthreads();

    // ---- epilogue: thread <-> token, +bias +LePE conv, store ----
    {
        const int n  = tid;
        const int ts = n >> 8;
        const int hs = (n >> 2) & 63;
        const int ws = n & 3;
        const int l  = ((tb * TSP + ts) * Hc + hs) * Wc + wb * WSP + ws;

        float acc[HD];
        #pragma unroll
        for (int d = 0; d < HD; d++) acc[d] = Osm[n * 34 + d] + Bsm[d];

        #pragma unroll
        for (int kt = -1; kt <= 1; kt++) {
            int tt = ts + kt;
            if (tt < 0 || tt >= TSP) continue;
            for (int kh = -1; kh <= 1; kh++) {
                int hh = hs + kh;
                if (hh < 0 || hh >= HSP) continue;
                #pragma unroll
                for (int kw = -1; kw <= 1; kw++) {
                    int wwi = ws + kw;
                    if (wwi < 0 || wwi >= WSP) continue;
                    int nbr = (tt * HSP + hh) * WSP + wwi;
                    int j   = (kt + 1) * 9 + (kh + 1) * 3 + (kw + 1);
                    const float* wr = Wsm + j * HD;
                    const uint4* vp = (const uint4*)(Vs + nbr * 40);
                    #pragma unroll
                    for (int q = 0; q < 4; q++) {
                        uint4 u = vp[q];
                        float2 f0 = __half22float2(*(__half2*)&u.x);
                        float2 f1 = __half22float2(*(__half2*)&u.y);
                        float2 f2 = __half22float2(*(__half2*)&u.z);
                        float2 f3 = __half22float2(*(__half2*)&u.w);
                        acc[8*q+0] += wr[8*q+0] * f0.x;
                        acc[8*q+1] += wr[8*q+1] * f0.y;
                        acc[8*q+2] += wr[8*q+2] * f1.x;
                        acc[8*q+3] += wr[8*q+3] * f1.y;
                        acc[8*q+4] += wr[8*q+4] * f2.x;
                        acc[8*q+5] += wr[8*q+5] * f2.y;
                        acc[8*q+6] += wr[8*q+6] * f3.x;
                        acc[8*q+7] += wr[8*q+7] * f3.y;
                    }
                }
            }
        }

        float* op = out + ((size_t)b * Lc + l) * Cc + cbase;
        #pragma unroll
        for (int f = 0; f < 8; f++)
            *(float4*)(op + f * 4) =
                make_float4(acc[f*4+0], acc[f*4+1], acc[f*4+2], acc[f*4+3]);
    }
}

extern "C" void kernel_launch(void* const* d_in, const int* in_sizes, int n_in,
                              void* d_out, int out_size)
{
    const float* qkv    = (const float*)d_in[0];
    const float* lepe_w = (const float*)d_in[1];
    const float* lepe_b = (const float*)d_in[2];
    float* out          = (float*)d_out;

    cudaFuncSetAttribute(lepe_attn_hmma,
                         cudaFuncAttributeMaxDynamicSharedMemorySize, SM_TOTAL);
    lepe_attn_hmma<<<Bc * (Tc / TSP) * (Wc / WSP) * 4, 512, SM_TOTAL>>>(
        qkv, lepe_w, lepe_b, out);
}